// round 2
// baseline (speedup 1.0000x reference)
#include <cuda_runtime.h>
#include <cstdint>

// Problem shape (fixed by the reference)
#define T_STEPS 5
#define BB 32
#define CC 128
#define HH 32
#define WW 32
#define HW (HH * WW)             // 1024
#define NPT (BB * CC * HW)       // 4,194,304 elements per timestep

static constexpr float V_TH    = 0.5f;
static constexpr float W_DEC   = 0.5f;
static constexpr float LOWER_C = 0.2f - 0.03f;   // 0.17
static constexpr float UPPER_C = 0.2f + 0.03f;   // 0.23
static constexpr float EMA0    = 0.17f;

// Scratch state (device globals — no allocation allowed in kernel_launch)
__device__ float g_mem[NPT];     // membrane potential carry
__device__ float g_ema[CC];      // per-channel EMA
__device__ float g_inhw[CC];     // per-channel inhibition weight
__device__ float g_chsum[CC];    // per-channel spike sum accumulator

__device__ __forceinline__ float sigmoidf(float x) {
    return 1.0f / (1.0f + expf(-x));
}

// Initialize per-channel state
__global__ void lif_init_channels() {
    int c = threadIdx.x;
    if (c < CC) {
        g_ema[c]   = EMA0;
        g_inhw[c]  = 0.0f;
        g_chsum[c] = 0.0f;
    }
}

// One LIF timestep. Each block owns exactly one (b,c) HW-plane of 1024
// elements (256 threads x float4), so the channel index is uniform per block.
// LAST=true skips the mem writeback and spike-count accumulation (unused
// after the final step).
template <bool LAST>
__global__ __launch_bounds__(256, 8)
void lif_step_kernel(const float* __restrict__ xe,
                     const float* __restrict__ xi,
                     const float* __restrict__ alpha_raw,
                     const float* __restrict__ beta_raw,
                     float* __restrict__ spike_out)
{
    const int bc   = blockIdx.x;            // 0 .. B*C-1
    const int c    = bc & (CC - 1);         // channel (uniform per block)
    const int base = bc * HW + threadIdx.x * 4;

    // Scalar params (tiny broadcast loads, L2/const-cached)
    const float alpha = 4.0f * sigmoidf(__ldg(alpha_raw));
    const float beta  = sigmoidf(__ldg(beta_raw));
    const float one_minus_inhw = 1.0f - __ldg(&g_inhw[c]);
    const float bw = beta * one_minus_inhw;

    const float4 xe4 = *reinterpret_cast<const float4*>(xe + base);
    const float4 xi4 = *reinterpret_cast<const float4*>(xi + base);
    float4 m4 = *reinterpret_cast<float4*>(g_mem + base);

    float cnt = 0.0f;
    float4 s4;

    {
        float m = W_DEC * m4.x + xe4.x / (1.0f + alpha * xi4.x) - bw * xi4.x;
        float s = (m >= V_TH) ? 1.0f : 0.0f;
        s4.x = s; m4.x = m - V_TH * s; cnt += s;
    }
    {
        float m = W_DEC * m4.y + xe4.y / (1.0f + alpha * xi4.y) - bw * xi4.y;
        float s = (m >= V_TH) ? 1.0f : 0.0f;
        s4.y = s; m4.y = m - V_TH * s; cnt += s;
    }
    {
        float m = W_DEC * m4.z + xe4.z / (1.0f + alpha * xi4.z) - bw * xi4.z;
        float s = (m >= V_TH) ? 1.0f : 0.0f;
        s4.z = s; m4.z = m - V_TH * s; cnt += s;
    }
    {
        float m = W_DEC * m4.w + xe4.w / (1.0f + alpha * xi4.w) - bw * xi4.w;
        float s = (m >= V_TH) ? 1.0f : 0.0f;
        s4.w = s; m4.w = m - V_TH * s; cnt += s;
    }

    *reinterpret_cast<float4*>(spike_out + base) = s4;

    if (!LAST) {
        *reinterpret_cast<float4*>(g_mem + base) = m4;

        // Block-level spike-count reduction -> one atomicAdd per block
        #pragma unroll
        for (int off = 16; off > 0; off >>= 1)
            cnt += __shfl_down_sync(0xFFFFFFFFu, cnt, off);

        __shared__ float warp_sums[8];
        const int lane = threadIdx.x & 31;
        const int wid  = threadIdx.x >> 5;
        if (lane == 0) warp_sums[wid] = cnt;
        __syncthreads();
        if (wid == 0) {
            float v = (lane < 8) ? warp_sums[lane] : 0.0f;
            #pragma unroll
            for (int off = 4; off > 0; off >>= 1)
                v += __shfl_down_sync(0xFFFFFFFFu, v, off);
            if (lane == 0) atomicAdd(&g_chsum[c], v);
        }
    }
}

// Per-channel EMA + inhibition-weight update between timesteps.
__global__ void lif_ema_kernel() {
    int c = threadIdx.x;
    if (c < CC) {
        const float mean = g_chsum[c] * (1.0f / (float)(BB * HW));
        const float ema  = 0.9f * g_ema[c] + 0.1f * mean;
        g_ema[c]  = ema;
        g_inhw[c] = 4.0f * (sigmoidf(LOWER_C - ema) - sigmoidf(ema - UPPER_C));
        g_chsum[c] = 0.0f;
    }
}

extern "C" void kernel_launch(void* const* d_in, const int* in_sizes, int n_in,
                              void* d_out, int out_size)
{
    const float* xe  = (const float*)d_in[0];  // x_exc  [T,B,C,H,W]
    const float* xi  = (const float*)d_in[1];  // x_inh  [T,B,C,H,W]
    const float* ar  = (const float*)d_in[2];  // alpha_raw scalar
    const float* br  = (const float*)d_in[3];  // beta_raw scalar
    float* out = (float*)d_out;                // spikes [T,B,C,H,W]

    // Zero the mem carry (deterministic per call; capturable memset node)
    void* memptr = nullptr;
    cudaGetSymbolAddress(&memptr, g_mem);
    cudaMemsetAsync(memptr, 0, (size_t)NPT * sizeof(float));

    lif_init_channels<<<1, CC>>>();

    const int grid = BB * CC;  // 4096 blocks, one HW-plane each
    for (int t = 0; t < T_STEPS; ++t) {
        const float* xet = xe + (size_t)t * NPT;
        const float* xit = xi + (size_t)t * NPT;
        float* st = out + (size_t)t * NPT;
        if (t < T_STEPS - 1) {
            lif_step_kernel<false><<<grid, 256>>>(xet, xit, ar, br, st);
            lif_ema_kernel<<<1, CC>>>();
        } else {
            lif_step_kernel<true><<<grid, 256>>>(xet, xit, ar, br, st);
        }
    }
}

// round 3
// speedup vs baseline: 1.0345x; 1.0345x over previous
#include <cuda_runtime.h>
#include <cstdint>

// Problem shape (fixed by the reference)
#define T_STEPS 5
#define BB 32
#define CC 128
#define HW 1024                   // 32*32
#define NPT (BB * CC * HW)        // 4,194,304 elements per timestep

#define NBLK 512                  // persistent grid: MUST all be co-resident
#define PLANES_PER_BLK 8          // 4096 (b,c) planes / 512 blocks

static constexpr float V_TH    = 0.5f;
static constexpr float W_DEC   = 0.5f;
static constexpr float LOWER_C = 0.2f - 0.03f;   // 0.17
static constexpr float UPPER_C = 0.2f + 0.03f;   // 0.23
static constexpr float EMA0    = 0.17f;

// Cross-block state (device globals — no allocation allowed)
__device__ float    g_chsum[T_STEPS - 1][CC];  // per-step spike sums (own buffer per step: no re-zero race)
__device__ unsigned g_bar;                     // grid barrier arrive counter

__device__ __forceinline__ float sigmoidf(float x) {
    return 1.0f / (1.0f + expf(-x));
}

// Tiny init: reset barrier counter and chsum buffers (runs every replay)
__global__ void lif_init() {
    if (threadIdx.x == 0) g_bar = 0u;
    for (int i = threadIdx.x; i < (T_STEPS - 1) * CC; i += blockDim.x)
        ((float*)g_chsum)[i] = 0.0f;
}

// Persistent kernel: all T steps in one launch. mem lives in SMEM; per-channel
// EMA/inhw replicated per block; software grid barrier between steps.
//
// Residency proof (required for the spin barrier):
//   static smem ~32.1KB -> 6 blocks/SM;  threads 2048/256 = 8 blocks/SM;
//   __launch_bounds__(256,4) -> regs <= 64 -> 4 blocks/SM (4*256*64 = 65536).
//   => 4 blocks/SM * 152 SMs = 608 >= NBLK=512. All blocks in wave 1.
__global__ __launch_bounds__(256, 4)
void lif_persistent(const float* __restrict__ xe,
                    const float* __restrict__ xi,
                    const float* __restrict__ alpha_raw,
                    const float* __restrict__ beta_raw,
                    float* __restrict__ out)
{
    __shared__ float s_mem[PLANES_PER_BLK * HW];   // 32 KB membrane carry
    __shared__ float s_ema[PLANES_PER_BLK];
    __shared__ float s_inhw[PLANES_PER_BLK];

    const int tid  = threadIdx.x;
    const int lane = tid & 31;
    const int w    = tid >> 5;                       // warp = one (b,c) plane
    const int plane = blockIdx.x * PLANES_PER_BLK + w;   // 0..4095
    const int c    = plane & (CC - 1);               // channel (uniform per warp)
    const size_t gbase = (size_t)plane * HW + lane * 4;
    const int    sbase = w * HW + lane * 4;

    // Zero the membrane carry in SMEM (replaces the 16.8MB global memset)
    #pragma unroll
    for (int j = 0; j < 8; ++j)
        *reinterpret_cast<float4*>(&s_mem[sbase + j * 128]) = make_float4(0.f, 0.f, 0.f, 0.f);
    if (tid < PLANES_PER_BLK) { s_ema[tid] = EMA0; s_inhw[tid] = 0.0f; }

    const float alpha = 4.0f * sigmoidf(__ldg(alpha_raw));
    const float beta  = sigmoidf(__ldg(beta_raw));
    __syncthreads();

    for (int t = 0; t < T_STEPS; ++t) {
        const float bw = beta * (1.0f - s_inhw[w]);
        const float* xet = xe  + (size_t)t * NPT + gbase;
        const float* xit = xi  + (size_t)t * NPT + gbase;
        float*       st  = out + (size_t)t * NPT + gbase;

        float cnt = 0.0f;
        #pragma unroll
        for (int j = 0; j < 8; ++j) {
            const int o = j * 128;   // warp covers 512B contiguous per j -> coalesced
            const float4 e4 = *reinterpret_cast<const float4*>(xet + o);
            const float4 i4 = *reinterpret_cast<const float4*>(xit + o);
            float4 m = *reinterpret_cast<float4*>(&s_mem[sbase + o]);
            float4 s;

            m.x = W_DEC * m.x + e4.x / (1.0f + alpha * i4.x) - bw * i4.x;
            s.x = (m.x >= V_TH) ? 1.0f : 0.0f;  m.x -= V_TH * s.x;
            m.y = W_DEC * m.y + e4.y / (1.0f + alpha * i4.y) - bw * i4.y;
            s.y = (m.y >= V_TH) ? 1.0f : 0.0f;  m.y -= V_TH * s.y;
            m.z = W_DEC * m.z + e4.z / (1.0f + alpha * i4.z) - bw * i4.z;
            s.z = (m.z >= V_TH) ? 1.0f : 0.0f;  m.z -= V_TH * s.z;
            m.w = W_DEC * m.w + e4.w / (1.0f + alpha * i4.w) - bw * i4.w;
            s.w = (m.w >= V_TH) ? 1.0f : 0.0f;  m.w -= V_TH * s.w;

            *reinterpret_cast<float4*>(st + o) = s;
            *reinterpret_cast<float4*>(&s_mem[sbase + o]) = m;
            cnt += s.x + s.y + s.z + s.w;
        }

        if (t < T_STEPS - 1) {
            // Per-plane (= per-warp) spike count -> one float atomic per warp
            #pragma unroll
            for (int off = 16; off > 0; off >>= 1)
                cnt += __shfl_down_sync(0xFFFFFFFFu, cnt, off);
            if (lane == 0) atomicAdd(&g_chsum[t][c], cnt);

            // ---- grid barrier ----
            __syncthreads();
            if (tid == 0) {
                __threadfence();                    // publish this block's atomics
                atomicAdd(&g_bar, 1u);
                const unsigned target = (unsigned)NBLK * (unsigned)(t + 1);
                while (*(volatile unsigned*)&g_bar < target) __nanosleep(64);
            }
            __syncthreads();

            // Per-channel EMA + inhibition update (replicated identically in
            // every block that touches the channel; reads via L2 atomics)
            if (tid < PLANES_PER_BLK) {
                const int cc = (blockIdx.x * PLANES_PER_BLK + tid) & (CC - 1);
                const float sum  = atomicAdd(&g_chsum[t][cc], 0.0f);
                const float ema  = 0.9f * s_ema[tid] + 0.1f * (sum * (1.0f / 32768.0f));
                s_ema[tid]  = ema;
                s_inhw[tid] = 4.0f * (sigmoidf(LOWER_C - ema) - sigmoidf(ema - UPPER_C));
            }
            __syncthreads();
        }
    }
}

extern "C" void kernel_launch(void* const* d_in, const int* in_sizes, int n_in,
                              void* d_out, int out_size)
{
    const float* xe = (const float*)d_in[0];  // x_exc  [T,B,C,H,W]
    const float* xi = (const float*)d_in[1];  // x_inh  [T,B,C,H,W]
    const float* ar = (const float*)d_in[2];  // alpha_raw scalar
    const float* br = (const float*)d_in[3];  // beta_raw scalar
    float* out = (float*)d_out;               // spikes [T,B,C,H,W]

    lif_init<<<1, 128>>>();
    lif_persistent<<<NBLK, 256>>>(xe, xi, ar, br, out);
}